// round 1
// baseline (speedup 1.0000x reference)
#include <cuda_runtime.h>
#include <math.h>

#define NQ 24
#define BATCH 4
#define DIMQ (1 << NQ)          // 2^24 rows
#define HALF (1 << (NQ - 1))    // 2^23 pair count
#define TPB 256

// One thread per pair index i in [0, 2^23).
// State (DIM, B=4) row-major -> each row is one float4 (all 4 batches).
// Pair partner row: i + 2^23 (qubit 0 = most significant axis).
// Output: (2, DIM, B): real plane then imag plane.
__global__ __launch_bounds__(TPB) void u_gate_kernel(
    const float4* __restrict__ sr,   // state_real as float4 rows
    const float4* __restrict__ si,   // state_imag as float4 rows
    const float*  __restrict__ thetas, // (3, 4): phi[4], theta[4], omega[4]
    float4* __restrict__ outr,       // out real plane, float4 rows
    float4* __restrict__ outi)       // out imag plane, float4 rows
{
    // u[b][0..7] = {u00r,u00i, u01r,u01i, u10r,u10i, u11r,u11i}
    __shared__ float u[BATCH * 8];

    const int tid = threadIdx.x;
    if (tid < BATCH) {
        float phi   = thetas[0 * BATCH + tid];
        float theta = thetas[1 * BATCH + tid];
        float omega = thetas[2 * BATCH + tid];
        float a = 0.5f * (phi + omega);
        float b = 0.5f * (phi - omega);
        float sa, ca, sb, cb, st, ct;
        sincosf(a, &sa, &ca);
        sincosf(b, &sb, &cb);
        sincosf(0.5f * theta, &st, &ct);
        // u00 = ct*(ca - i sa); u01 = -st*(cb + i sb)
        // u10 = st*(cb - i sb); u11 = ct*(ca + i sa)
        float* ub = &u[tid * 8];
        ub[0] =  ct * ca;  ub[1] = -ct * sa;
        ub[2] = -st * cb;  ub[3] = -st * sb;
        ub[4] =  st * cb;  ub[5] = -st * sb;
        ub[6] =  ct * ca;  ub[7] =  ct * sa;
    }
    __syncthreads();

    const unsigned i0 = blockIdx.x * TPB + tid;  // pair index, < 2^23
    const unsigned i1 = i0 + HALF;

    // 4 independent 16B loads -> MLP 4
    float4 s0r = __ldg(&sr[i0]);
    float4 s0i = __ldg(&si[i0]);
    float4 s1r = __ldg(&sr[i1]);
    float4 s1i = __ldg(&si[i1]);

    float4 o0r, o0i, o1r, o1i;

    const float* s0rf = (const float*)&s0r;
    const float* s0if = (const float*)&s0i;
    const float* s1rf = (const float*)&s1r;
    const float* s1if = (const float*)&s1i;
    float* o0rf = (float*)&o0r;
    float* o0if = (float*)&o0i;
    float* o1rf = (float*)&o1r;
    float* o1if = (float*)&o1i;

#pragma unroll
    for (int b = 0; b < BATCH; b++) {
        float u00r = u[b*8+0], u00i = u[b*8+1];
        float u01r = u[b*8+2], u01i = u[b*8+3];
        float u10r = u[b*8+4], u10i = u[b*8+5];
        float u11r = u[b*8+6], u11i = u[b*8+7];
        float x0r = s0rf[b], x0i = s0if[b];
        float x1r = s1rf[b], x1i = s1if[b];

        o0rf[b] = u00r*x0r - u00i*x0i + u01r*x1r - u01i*x1i;
        o0if[b] = u00r*x0i + u00i*x0r + u01r*x1i + u01i*x1r;
        o1rf[b] = u10r*x0r - u10i*x0i + u11r*x1r - u11i*x1i;
        o1if[b] = u10r*x0i + u10i*x0r + u11r*x1i + u11i*x1r;
    }

    outr[i0] = o0r;
    outi[i0] = o0i;
    outr[i1] = o1r;
    outi[i1] = o1i;
}

extern "C" void kernel_launch(void* const* d_in, const int* in_sizes, int n_in,
                              void* d_out, int out_size)
{
    const float4* sr = (const float4*)d_in[0];   // state_real (DIM, 4)
    const float4* si = (const float4*)d_in[1];   // state_imag (DIM, 4)
    const float*  th = (const float*)d_in[2];    // thetas (3, 4)

    float4* outr = (float4*)d_out;               // real plane: DIM float4 rows
    float4* outi = outr + DIMQ;                  // imag plane

    dim3 grid(HALF / TPB);  // 32768 blocks
    u_gate_kernel<<<grid, TPB>>>(sr, si, th, outr, outi);
}

// round 2
// speedup vs baseline: 1.0065x; 1.0065x over previous
#include <cuda_runtime.h>
#include <math.h>

#define NQ 24
#define BATCH 4
#define DIMQ (1 << NQ)          // 2^24 rows
#define HALF (1 << (NQ - 1))    // 2^23 pair count
#define TPB 256
#define PAIRS_PER_THREAD 2

// One thread handles 2 pair indices (consecutive TPB-strided tiles for
// coalescing). State (DIM, B=4) row-major -> each row is one float4.
// Pair partner row: i + 2^23 (qubit 0 = most significant axis).
// Output (2, DIM, B): real plane then imag plane.
// All global traffic uses streaming hints (.cs) - zero reuse workload.
__global__ __launch_bounds__(TPB) void u_gate_kernel(
    const float4* __restrict__ sr,
    const float4* __restrict__ si,
    const float*  __restrict__ thetas,  // (3,4): phi[4], theta[4], omega[4]
    float4* __restrict__ outr,
    float4* __restrict__ outi)
{
    // u[b][0..7] = {u00r,u00i, u01r,u01i, u10r,u10i, u11r,u11i}
    __shared__ float u[BATCH * 8];

    const int tid = threadIdx.x;
    if (tid < BATCH) {
        float phi   = thetas[0 * BATCH + tid];
        float theta = thetas[1 * BATCH + tid];
        float omega = thetas[2 * BATCH + tid];
        float a = 0.5f * (phi + omega);
        float b = 0.5f * (phi - omega);
        float sa, ca, sb, cb, st, ct;
        sincosf(a, &sa, &ca);
        sincosf(b, &sb, &cb);
        sincosf(0.5f * theta, &st, &ct);
        float* ub = &u[tid * 8];
        ub[0] =  ct * ca;  ub[1] = -ct * sa;
        ub[2] = -st * cb;  ub[3] = -st * sb;
        ub[4] =  st * cb;  ub[5] = -st * sb;
        ub[6] =  ct * ca;  ub[7] =  ct * sa;
    }
    __syncthreads();

    // Pull the 4 matrices into registers once (broadcast LDS, no conflicts).
    float ur[BATCH][8];
#pragma unroll
    for (int b = 0; b < BATCH; b++)
#pragma unroll
        for (int k = 0; k < 8; k++)
            ur[b][k] = u[b * 8 + k];

    const unsigned base = blockIdx.x * (TPB * PAIRS_PER_THREAD) + tid;

    unsigned idx0[PAIRS_PER_THREAD];
#pragma unroll
    for (int p = 0; p < PAIRS_PER_THREAD; p++)
        idx0[p] = base + p * TPB;

    // 8 independent 16B streaming loads -> MLP 8
    float4 s0r[PAIRS_PER_THREAD], s0i[PAIRS_PER_THREAD];
    float4 s1r[PAIRS_PER_THREAD], s1i[PAIRS_PER_THREAD];
#pragma unroll
    for (int p = 0; p < PAIRS_PER_THREAD; p++) {
        s0r[p] = __ldcs(&sr[idx0[p]]);
        s0i[p] = __ldcs(&si[idx0[p]]);
        s1r[p] = __ldcs(&sr[idx0[p] + HALF]);
        s1i[p] = __ldcs(&si[idx0[p] + HALF]);
    }

#pragma unroll
    for (int p = 0; p < PAIRS_PER_THREAD; p++) {
        float4 o0r, o0i, o1r, o1i;
        const float* s0rf = (const float*)&s0r[p];
        const float* s0if = (const float*)&s0i[p];
        const float* s1rf = (const float*)&s1r[p];
        const float* s1if = (const float*)&s1i[p];
        float* o0rf = (float*)&o0r;
        float* o0if = (float*)&o0i;
        float* o1rf = (float*)&o1r;
        float* o1if = (float*)&o1i;

#pragma unroll
        for (int b = 0; b < BATCH; b++) {
            float u00r = ur[b][0], u00i = ur[b][1];
            float u01r = ur[b][2], u01i = ur[b][3];
            float u10r = ur[b][4], u10i = ur[b][5];
            float u11r = ur[b][6], u11i = ur[b][7];
            float x0r = s0rf[b], x0i = s0if[b];
            float x1r = s1rf[b], x1i = s1if[b];

            o0rf[b] = u00r*x0r - u00i*x0i + u01r*x1r - u01i*x1i;
            o0if[b] = u00r*x0i + u00i*x0r + u01r*x1i + u01i*x1r;
            o1rf[b] = u10r*x0r - u10i*x0i + u11r*x1r - u11i*x1i;
            o1if[b] = u10r*x0i + u10i*x0r + u11r*x1i + u11i*x1r;
        }

        __stcs(&outr[idx0[p]], o0r);
        __stcs(&outi[idx0[p]], o0i);
        __stcs(&outr[idx0[p] + HALF], o1r);
        __stcs(&outi[idx0[p] + HALF], o1i);
    }
}

extern "C" void kernel_launch(void* const* d_in, const int* in_sizes, int n_in,
                              void* d_out, int out_size)
{
    const float4* sr = (const float4*)d_in[0];   // state_real (DIM, 4)
    const float4* si = (const float4*)d_in[1];   // state_imag (DIM, 4)
    const float*  th = (const float*)d_in[2];    // thetas (3, 4)

    float4* outr = (float4*)d_out;               // real plane
    float4* outi = outr + DIMQ;                  // imag plane

    dim3 grid(HALF / (TPB * PAIRS_PER_THREAD));  // 16384 blocks
    u_gate_kernel<<<grid, TPB>>>(sr, si, th, outr, outi);
}

// round 3
// speedup vs baseline: 1.0102x; 1.0037x over previous
#include <cuda_runtime.h>
#include <math.h>

#define NQ 24
#define BATCH 4
#define DIMQ (1 << NQ)          // 2^24 rows
#define HALF (1 << (NQ - 1))    // 2^23 pair count
#define TPB 512

// One thread per pair index i in [0, 2^23).
// State (DIM, B=4) row-major -> each row is one float4 (all 4 batches).
// Pair partner row: i + 2^23 (qubit 0 = most significant axis).
// Output: (2, DIM, B): real plane then imag plane.
// Streaming cache hints: zero-reuse workload, keep L2 for write coalescing.
__global__ __launch_bounds__(TPB) void u_gate_kernel(
    const float4* __restrict__ sr,
    const float4* __restrict__ si,
    const float*  __restrict__ thetas,  // (3,4): phi[4], theta[4], omega[4]
    float4* __restrict__ outr,
    float4* __restrict__ outi)
{
    // u[b][0..7] = {u00r,u00i, u01r,u01i, u10r,u10i, u11r,u11i}
    __shared__ float u[BATCH * 8];

    const int tid = threadIdx.x;
    if (tid < BATCH) {
        float phi   = thetas[0 * BATCH + tid];
        float theta = thetas[1 * BATCH + tid];
        float omega = thetas[2 * BATCH + tid];
        float a = 0.5f * (phi + omega);
        float b = 0.5f * (phi - omega);
        float sa, ca, sb, cb, st, ct;
        sincosf(a, &sa, &ca);
        sincosf(b, &sb, &cb);
        sincosf(0.5f * theta, &st, &ct);
        // u00 = ct*(ca - i sa); u01 = -st*(cb + i sb)
        // u10 = st*(cb - i sb); u11 = ct*(ca + i sa)
        float* ub = &u[tid * 8];
        ub[0] =  ct * ca;  ub[1] = -ct * sa;
        ub[2] = -st * cb;  ub[3] = -st * sb;
        ub[4] =  st * cb;  ub[5] = -st * sb;
        ub[6] =  ct * ca;  ub[7] =  ct * sa;
    }
    __syncthreads();

    const unsigned i0 = blockIdx.x * TPB + tid;  // pair index, < 2^23
    const unsigned i1 = i0 + HALF;

    // 4 independent 16B streaming loads (evict-first in L2)
    float4 s0r = __ldcs(&sr[i0]);
    float4 s0i = __ldcs(&si[i0]);
    float4 s1r = __ldcs(&sr[i1]);
    float4 s1i = __ldcs(&si[i1]);

    float4 o0r, o0i, o1r, o1i;

    const float* s0rf = (const float*)&s0r;
    const float* s0if = (const float*)&s0i;
    const float* s1rf = (const float*)&s1r;
    const float* s1if = (const float*)&s1i;
    float* o0rf = (float*)&o0r;
    float* o0if = (float*)&o0i;
    float* o1rf = (float*)&o1r;
    float* o1if = (float*)&o1i;

#pragma unroll
    for (int b = 0; b < BATCH; b++) {
        float u00r = u[b*8+0], u00i = u[b*8+1];
        float u01r = u[b*8+2], u01i = u[b*8+3];
        float u10r = u[b*8+4], u10i = u[b*8+5];
        float u11r = u[b*8+6], u11i = u[b*8+7];
        float x0r = s0rf[b], x0i = s0if[b];
        float x1r = s1rf[b], x1i = s1if[b];

        o0rf[b] = u00r*x0r - u00i*x0i + u01r*x1r - u01i*x1i;
        o0if[b] = u00r*x0i + u00i*x0r + u01r*x1i + u01i*x1r;
        o1rf[b] = u10r*x0r - u10i*x0i + u11r*x1r - u11i*x1i;
        o1if[b] = u10r*x0i + u10i*x0r + u11r*x1i + u11i*x1r;
    }

    __stcs(&outr[i0], o0r);
    __stcs(&outi[i0], o0i);
    __stcs(&outr[i1], o1r);
    __stcs(&outi[i1], o1i);
}

extern "C" void kernel_launch(void* const* d_in, const int* in_sizes, int n_in,
                              void* d_out, int out_size)
{
    const float4* sr = (const float4*)d_in[0];   // state_real (DIM, 4)
    const float4* si = (const float4*)d_in[1];   // state_imag (DIM, 4)
    const float*  th = (const float*)d_in[2];    // thetas (3, 4)

    float4* outr = (float4*)d_out;               // real plane
    float4* outi = outr + DIMQ;                  // imag plane

    dim3 grid(HALF / TPB);  // 16384 blocks of 512
    u_gate_kernel<<<grid, TPB>>>(sr, si, th, outr, outi);
}